// round 10
// baseline (speedup 1.0000x reference)
#include <cuda_runtime.h>
#include <cuda_fp16.h>
#include <cstdint>
#include <cstddef>

#define DD     256
#define LL     3
#define NSEQ   6300
#define TSq    5400
#define BBn    16
#define MROWS  (BBn*NSEQ)
#define FBROWS (BBn*900)
#define DSLOT  145
#define INV_SQRT_DC 0.08838834764831843f
#define S_OP  64.0f
#define S_SC  1024.0f
#define S_QF  524288.0f
#define KVCH  32          // kv accumulation chunks

typedef __half hf;

// ---------------- fp32 scratch ----------------
__device__ __align__(16) float g_cur [(size_t)MROWS*DD];
__device__ __align__(16) float g_h   [(size_t)MROWS*DD];
__device__ __align__(16) float g_sc  [(size_t)MROWS*64];
__device__ __align__(16) float g_qkv [(size_t)MROWS*768];
__device__ __align__(16) float g_cache[BBn*48*DSLOT];
__device__ __align__(16) float g_ks  [64*64];
__device__ __align__(16) float g_kvp [(size_t)KVCH*64*4096];
__device__ __align__(16) float g_ksp [KVCH*64*64];
__device__ __align__(16) float g_kvf [64*4096];
__device__ __align__(16) float g_kcf [16*48*128];
__device__ __align__(16) float g_wk  [BBn*64*128];
__device__ __align__(16) float g_wv  [BBn*64*128];
__device__ __align__(16) float g_cos [NSEQ*32];
__device__ __align__(16) float g_sin [NSEQ*32];
__device__ __align__(16) float g_logits[FBROWS*16];
__device__ __align__(16) float g_fbin [(size_t)FBROWS*512];
__device__ __align__(16) float g_fbout[(size_t)FBROWS*256];

// ---------------- fp16 hi/lo splits (scaled) ----------------
__device__ __align__(16) hf g_hh [(size_t)MROWS*256];
__device__ __align__(16) hf g_hl [(size_t)MROWS*256];
__device__ __align__(16) hf g_sch[(size_t)MROWS*64];
__device__ __align__(16) hf g_scl[(size_t)MROWS*64];
__device__ __align__(16) hf g_qfh[(size_t)MROWS*256];
__device__ __align__(16) hf g_qfl[(size_t)MROWS*256];
__device__ __align__(16) hf g_fbih[(size_t)FBROWS*512];
__device__ __align__(16) hf g_fbil[(size_t)FBROWS*512];
__device__ __align__(16) hf g_kqh[16*64*256],  g_kql[16*64*256];
__device__ __align__(16) hf g_vch[16*256*64],  g_vcl[16*256*64];
__device__ __align__(16) hf g_mth[16*256*256], g_mtl[16*256*256];
__device__ __align__(16) hf g_wqkvh[3*768*256],g_wqkvl[3*768*256];
__device__ __align__(16) hf g_wfbh[256*512],   g_wfbl[256*512];

__device__ __forceinline__ float sigm(float x){ return 1.f/(1.f+expf(-x)); }
__device__ __forceinline__ float elu1(float x){ return x>0.f ? x+1.f : expf(x); }

__device__ __forceinline__ void wsph(hf* ph, hf* pl, size_t i, float x){
    hf h = __float2half_rn(x);
    ph[i] = h;
    pl[i] = __float2half_rn(x - __half2float(h));
}

// ---------------- init ----------------
__global__ void k_init(const float* __restrict__ se, const float* __restrict__ lid){
    int i = blockIdx.x*256 + threadIdx.x;
    if (i < NSEQ*32){
        int n = i/32, j = i%32;
        float inv = 1.f/powf(10000.f, (float)(2*j)/64.f);
        float f = (float)n * inv;
        g_cos[i] = cosf(f);
        g_sin[i] = sinf(f);
    }
    if (i < BBn*48*DSLOT){
        int r2 = i % (48*DSLOT);
        int slot = r2 / DSLOT, c = r2 % DSLOT;
        float v = 0.f;
        if (c < 128)                  v = se[slot*128 + c];
        else if (c >= 129 && c < 137) v = lid[(slot/16)*8 + (c-129)];
        g_cache[i] = v;
    }
}

__global__ void k_embed(const int* __restrict__ di, const int* __restrict__ dou,
                        const int* __restrict__ ti, const float* __restrict__ tok,
                        const float* __restrict__ seg){
    int n = blockIdx.x, b = blockIdx.y, t = threadIdx.x;
    int tk;
    if (n < TSq){
        int d = n/1800, rem = n%1800, w = rem/900, s = rem%900;
        tk = w ? dou[(b*3+d)*900+s] : di[(b*3+d)*900+s];
    } else {
        tk = ti[b*900 + (n-TSq)];
    }
    g_cur[((size_t)b*NSEQ+n)*DD + t] = tok[tk*DD+t] + seg[t];
}

__global__ void k_copy(){
    size_t i = ((size_t)blockIdx.x*256 + threadIdx.x)*4;
    float4 v = *(const float4*)(g_cur + i);
    *(float4*)(g_h + i) = v;
    wsph(g_hh, g_hl, i+0, v.x*S_OP);
    wsph(g_hh, g_hl, i+1, v.y*S_OP);
    wsph(g_hh, g_hl, i+2, v.z*S_OP);
    wsph(g_hh, g_hl, i+3, v.w*S_OP);
}

// merged weight transpose+split (Wqkv, Wfb)
__device__ __forceinline__ void wtsplit(const float* src, hf* dh, hf* dl,
                                        int idx, int KK, int NN){
    int l = idx/(KK*NN), rem = idx%(KK*NN);
    int k = rem/NN, n = rem%NN;
    float x = src[idx]*S_OP;
    size_t o = (size_t)l*KK*NN + (size_t)n*KK + k;
    hf h = __float2half_rn(x);
    dh[o] = h;
    dl[o] = __float2half_rn(x - __half2float(h));
}

__global__ void k_wsplit_all(const float* __restrict__ Wqkv, const float* __restrict__ Wfb){
    int idx = blockIdx.x*256 + threadIdx.x;
    if (idx < 589824){ wtsplit(Wqkv, g_wqkvh, g_wqkvl, idx, 256, 768); return; }
    idx -= 589824;
    if (idx < 131072){ wtsplit(Wfb, g_wfbh, g_wfbl, idx, 512, 256); return; }
}

// ---------------- MMA helpers ----------------
__device__ __forceinline__ void mma_f32(float* c, const uint32_t* a, const uint32_t* b){
    asm volatile(
      "mma.sync.aligned.m16n8k16.row.col.f32.f16.f16.f32 "
      "{%0,%1,%2,%3},{%4,%5,%6,%7},{%8,%9},{%0,%1,%2,%3};\n"
      : "+f"(c[0]),"+f"(c[1]),"+f"(c[2]),"+f"(c[3])
      : "r"(a[0]),"r"(a[1]),"r"(a[2]),"r"(a[3]), "r"(b[0]),"r"(b[1]));
}
__device__ __forceinline__ void mma_f16(uint32_t* c, const uint32_t* a, const uint32_t* b){
    asm volatile(
      "mma.sync.aligned.m16n8k16.row.col.f16.f16.f16.f16 "
      "{%0,%1},{%2,%3,%4,%5},{%6,%7},{%0,%1};\n"
      : "+r"(c[0]),"+r"(c[1])
      : "r"(a[0]),"r"(a[1]),"r"(a[2]),"r"(a[3]), "r"(b[0]),"r"(b[1]));
}
__device__ __forceinline__ void ldsm4(uint32_t& r0,uint32_t& r1,uint32_t& r2,uint32_t& r3,
                                      uint32_t addr){
    asm volatile("ldmatrix.sync.aligned.m8n8.x4.shared.b16 {%0,%1,%2,%3}, [%4];\n"
        : "=r"(r0),"=r"(r1),"=r"(r2),"=r"(r3) : "r"(addr));
}

// ---------------- fp16 3-term GEMM, 4-stage pipeline, 2 CTAs/SM ----------------
#define STGB 18432
__global__ void __launch_bounds__(256,2) k_gemm_h(
    const hf* __restrict__ Ah, const hf* __restrict__ Al,
    const hf* __restrict__ Bh, const hf* __restrict__ Bl,
    float* C, hf* Ch, hf* Cl,
    int M, int K, int lda, int ldb, int ldc,
    int bdiv, long sA1, long sA2, long sB1, long sB2, long sC1, long sC2,
    int flags, float alpha)
{
    extern __shared__ __align__(16) char smem_raw[];
    uint32_t smem_u32 = (uint32_t)__cvta_generic_to_shared(smem_raw);

    int bz = blockIdx.z;
    int b1 = bz / bdiv, b2 = bz % bdiv;
    Ah += (size_t)b1*sA1 + (size_t)b2*sA2;
    Al += (size_t)b1*sA1 + (size_t)b2*sA2;
    Bh += (size_t)b1*sB1 + (size_t)b2*sB2;
    Bl += (size_t)b1*sB1 + (size_t)b2*sB2;
    size_t coff = (size_t)b1*sC1 + (size_t)b2*sC2;

    const int t = threadIdx.x;
    const int lane = t & 31, wid = t >> 5;
    const int g = lane >> 2, t4 = lane & 3;
    const int wm = wid & 3, wn = wid >> 2;
    const int row0 = blockIdx.y*128;
    const int col0 = blockIdx.x*64;

    const int sel = lane >> 3, rr = lane & 7;
    const int aoff = (wm*32 + (sel&1)*8 + rr)*48 + ((sel>>1)*8)*2;
    const int boff = (wn*32 + (sel>>1)*8 + rr)*48 + ((sel&1)*8)*2;

    float    acc[2][4][4];
    uint32_t acl[2][4][2];
    #pragma unroll
    for (int i=0;i<2;i++)
        #pragma unroll
        for (int j=0;j<4;j++){
            #pragma unroll
            for (int q=0;q<4;q++) acc[i][j][q]=0.f;
            acl[i][j][0]=0u; acl[i][j][1]=0u;
        }

    const int nk = K >> 4;

    auto load_stage = [&](int kt, int stage){
        uint32_t sb = smem_u32 + stage*STGB;
        #pragma unroll
        for (int pass=0; pass<3; pass++){
            int c = t + pass*256;
            if (c < 512){
                int mat  = c >> 8;
                int r    = (c >> 1) & 127;
                int half = c & 1;
                bool ok = (row0 + r) < M;
                int rc = ok ? r : 0;
                const hf* src = (mat ? Al : Ah) + (size_t)(row0+rc)*lda + kt*16 + half*8;
                uint32_t dst = sb + mat*6144 + r*48 + half*16;
                int sz = ok ? 16 : 0;
                asm volatile("cp.async.ca.shared.global [%0], [%1], 16, %2;\n"
                             :: "r"(dst), "l"(src), "r"(sz));
            } else {
                int c2 = c - 512;
                int bmat = c2 >> 7;
                int rem  = c2 & 127;
                int r = rem >> 1, half = rem & 1;
                const hf* src = (bmat ? Bl : Bh) + (size_t)(col0+r)*ldb + kt*16 + half*8;
                uint32_t dst = sb + 12288 + bmat*3072 + r*48 + half*16;
                asm volatile("cp.async.ca.shared.global [%0], [%1], 16, 16;\n"
                             :: "r"(dst), "l"(src));
            }
        }
    };

    #pragma unroll
    for (int p=0; p<3; p++){
        if (p < nk) load_stage(p, p);
        asm volatile("cp.async.commit_group;\n");
    }

    for (int kt=0; kt<nk; kt++){
        asm volatile("cp.async.wait_group 2;\n");
        __syncthreads();
        int kn = kt + 3;
        if (kn < nk) load_stage(kn, kn & 3);
        asm volatile("cp.async.commit_group;\n");

        uint32_t sb = smem_u32 + (kt & 3)*STGB;
        uint32_t ah[2][4], al_[2][4], bh_[4][2], bl_[4][2];
        #pragma unroll
        for (int mt=0; mt<2; mt++){
            ldsm4(ah[mt][0],ah[mt][1],ah[mt][2],ah[mt][3],     sb + aoff + mt*768);
            ldsm4(al_[mt][0],al_[mt][1],al_[mt][2],al_[mt][3], sb + 6144 + aoff + mt*768);
        }
        #pragma unroll
        for (int ntp=0; ntp<2; ntp++){
            uint32_t r0,r1,r2,r3;
            ldsm4(r0,r1,r2,r3, sb + 12288 + boff + ntp*768);
            bh_[2*ntp][0]=r0; bh_[2*ntp][1]=r1; bh_[2*ntp+1][0]=r2; bh_[2*ntp+1][1]=r3;
            ldsm4(r0,r1,r2,r3, sb + 15360 + boff + ntp*768);
            bl_[2*ntp][0]=r0; bl_[2*ntp][1]=r1; bl_[2*ntp+1][0]=r2; bl_[2*ntp+1][1]=r3;
        }
        #pragma unroll
        for (int mt=0; mt<2; mt++){
            #pragma unroll
            for (int nt=0; nt<4; nt++){
                mma_f32(acc[mt][nt], ah[mt],  bh_[nt]);
                mma_f16(acl[mt][nt], ah[mt],  bl_[nt]);
                mma_f16(acl[mt][nt], al_[mt], bh_[nt]);
            }
        }
    }

    #pragma unroll
    for (int mt=0; mt<2; mt++){
        #pragma unroll
        for (int nt=0; nt<4; nt++){
            int col = col0 + wn*32 + nt*8 + t4*2;
            __half2 lo0 = *(__half2*)&acl[mt][nt][0];
            __half2 lo1 = *(__half2*)&acl[mt][nt][1];
            float cx[4];
            cx[0] = __half2float(lo0.x); cx[1] = __half2float(lo0.y);
            cx[2] = __half2float(lo1.x); cx[3] = __half2float(lo1.y);
            #pragma unroll
            for (int hrow=0; hrow<2; hrow++){
                int r = row0 + wm*32 + mt*16 + g + hrow*8;
                if (r >= M) continue;
                float x = alpha*(acc[mt][nt][hrow*2+0] + cx[hrow*2+0]);
                float y = alpha*(acc[mt][nt][hrow*2+1] + cx[hrow*2+1]);
                size_t off = coff + (size_t)r*ldc + col;
                if (flags & 2){ x += C[off]; y += C[off+1]; }
                if (flags & 1){ C[off] = x; C[off+1] = y; }
                if (flags & 4){
                    float xs = x*S_OP, ys = y*S_OP;
                    hf xh = __float2half_rn(xs);
                    hf yh = __float2half_rn(ys);
                    __half2 ph; ph.x = xh; ph.y = yh;
                    *(__half2*)(Ch + off) = ph;
                    __half2 pl;
                    pl.x = __float2half_rn(xs - __half2float(xh));
                    pl.y = __float2half_rn(ys - __half2float(yh));
                    *(__half2*)(Cl + off) = pl;
                }
            }
        }
    }
}

// ---------------- cache k (fp32) and v (split) projections — 4-acc ILP ----------------
__global__ void k_cachekv(const float* __restrict__ Wk, const float* __restrict__ Wv){
    int idx = blockIdx.x*256 + threadIdx.x;
    if (idx >= BBn*22528) return;
    int b = idx / 22528, o = idx % 22528;
    const float* cb = g_cache + (size_t)b*48*DSLOT;
    if (o < 6144){
        int m = o >> 7, d = o & 127;
        const float* row = cb + (size_t)m*DSLOT;
        const float* wp  = Wk + d;
        float a0=0.f,a1=0.f,a2=0.f,a3=0.f;
        #pragma unroll 4
        for (int dd=0; dd<144; dd+=4){
            a0 += row[dd+0]*wp[(dd+0)*128];
            a1 += row[dd+1]*wp[(dd+1)*128];
            a2 += row[dd+2]*wp[(dd+2)*128];
            a3 += row[dd+3]*wp[(dd+3)*128];
        }
        a0 += row[144]*wp[144*128];
        g_kcf[(b*48+m)*128 + d] = (a0+a1)+(a2+a3);
    } else {
        int o2 = o - 6144;
        int j = o2 >> 6, m = o2 & 63;
        float a = 0.f;
        if (m < 48){
            const float* row = cb + (size_t)m*DSLOT;
            const float* wp  = Wv + j;
            float a0=0.f,a1=0.f,a2=0.f,a3=0.f;
            #pragma unroll 4
            for (int dd=0; dd<144; dd+=4){
                a0 += row[dd+0]*wp[(dd+0)*256];
                a1 += row[dd+1]*wp[(dd+1)*256];
                a2 += row[dd+2]*wp[(dd+2)*256];
                a3 += row[dd+3]*wp[(dd+3)*256];
            }
            a0 += row[144]*wp[144*256];
            a = (a0+a1)+(a2+a3);
        }
        wsph(g_vch, g_vcl, (size_t)b*16384 + (size_t)j*64 + m, a*S_OP);
    }
}

// ---------------- KQ = kc @ Wq^T (float4, 4-acc) ----------------
__global__ void k_kq(const float* __restrict__ Wq){
    int idx = blockIdx.x*256 + threadIdx.x;
    if (idx >= 262144) return;
    int b  = idx >> 14;
    int d  = (idx >> 6) & 255;
    int m  = idx & 63;
    float a = 0.f;
    if (m < 48){
        const float4* kc = (const float4*)(g_kcf + (b*48 + m)*128);
        const float4* wq = (const float4*)(Wq + d*128);
        float a0=0.f,a1=0.f,a2=0.f,a3=0.f;
        #pragma unroll 8
        for (int c=0; c<32; c+=4){
            float4 k0=kc[c+0], w0=wq[c+0];
            float4 k1=kc[c+1], w1=wq[c+1];
            float4 k2=kc[c+2], w2=wq[c+2];
            float4 k3=kc[c+3], w3=wq[c+3];
            a0 += k0.x*w0.x + k0.y*w0.y + k0.z*w0.z + k0.w*w0.w;
            a1 += k1.x*w1.x + k1.y*w1.y + k1.z*w1.z + k1.w*w1.w;
            a2 += k2.x*w2.x + k2.y*w2.y + k2.z*w2.z + k2.w*w2.w;
            a3 += k3.x*w3.x + k3.y*w3.y + k3.z*w3.z + k3.w*w3.w;
        }
        a = (a0+a1)+(a2+a3);
    }
    wsph(g_kqh, g_kql, ((size_t)b*64 + m)*256 + d, a*S_OP);
}

// ---------------- softmax + rgate fold ----------------
__global__ void k_softrg(const float* __restrict__ Wg, const float* __restrict__ bg, int l){
    int gw = blockIdx.x*8 + (threadIdx.x>>5);
    int lane = threadIdx.x & 31;
    if (gw >= MROWS) return;
    const float* hrow = g_h + (size_t)gw*256;
    const float* wg = Wg + l*256;
    float pg = 0.f;
    #pragma unroll
    for (int j=0;j<8;j++) pg += hrow[lane + 32*j]*wg[lane + 32*j];
    #pragma unroll
    for (int o=16;o;o>>=1) pg += __shfl_xor_sync(0xffffffffu, pg, o);
    float rgate = sigm(pg + bg[l]);
    const float* scp = g_sc + (size_t)gw*64;
    float s0 = scp[lane]*INV_SQRT_DC;
    float s1 = (lane<16) ? scp[lane+32]*INV_SQRT_DC : -1e30f;
    float mx = fmaxf(s0, s1);
    #pragma unroll
    for (int o=16;o;o>>=1) mx = fmaxf(mx, __shfl_xor_sync(0xffffffffu, mx, o));
    float e0 = expf(s0-mx);
    float e1 = (lane<16) ? expf(s1-mx) : 0.f;
    float su = e0+e1;
    #pragma unroll
    for (int o=16;o;o>>=1) su += __shfl_xor_sync(0xffffffffu, su, o);
    float sc = rgate*S_SC/su;
    wsph(g_sch, g_scl, (size_t)gw*64 + lane, e0*sc);
    wsph(g_sch, g_scl, (size_t)gw*64 + lane + 32, (lane<16) ? e1*sc : 0.f);
}

// ---------------- linear attention: kv / ksum partials (32 chunks) ----------------
__global__ void __launch_bounds__(256) k_kvacc(){
    int bh = blockIdx.y;
    int b = bh >> 2, h = bh & 3;
    int n0 = blockIdx.x*200;
    __shared__ float kf[4*64];
    __shared__ float vh[4*64];
    int t = threadIdx.x;
    int d = t >> 2, eb = (t & 3) << 4;
    float acc[16];
    #pragma unroll
    for (int j=0;j<16;j++) acc[j]=0.f;
    float ksa = 0.f;
    for (int nb=0; nb<200; nb+=4){
        int nbase = n0 + nb;
        if (t < 128){
            int sub = t>>5, i2 = t&31;
            int n = nbase + sub;
            float v1=0.f, v2=0.f;
            if (n < NSEQ){
                const float* bp = g_qkv + (size_t)(b*NSEQ+n)*768 + 256 + h*64;
                float x1=bp[2*i2], x2=bp[2*i2+1];
                float c=g_cos[n*32+i2], s=g_sin[n*32+i2];
                v1 = elu1(x1*c - x2*s);
                v2 = elu1(x1*s + x2*c);
            }
            kf[sub*64+2*i2]=v1; kf[sub*64+2*i2+1]=v2;
        } else {
            int t2 = t-128;
            #pragma unroll
            for (int q2=0;q2<2;q2++){
                int idx = t2 + q2*128;
                int sub = idx>>6, j = idx&63;
                int n = nbase + sub;
                vh[sub*64+j] = (n<NSEQ) ? g_qkv[(size_t)(b*NSEQ+n)*768 + 512 + h*64 + j] : 0.f;
            }
        }
        __syncthreads();
        #pragma unroll
        for (int sub=0; sub<4; sub++){
            float kd = kf[sub*64+d];
            ksa += kd;
            const float4* vp = (const float4*)&vh[sub*64+eb];
            #pragma unroll
            for (int q4=0;q4<4;q4++){
                float4 v4 = vp[q4];
                acc[q4*4+0]+=kd*v4.x; acc[q4*4+1]+=kd*v4.y;
                acc[q4*4+2]+=kd*v4.z; acc[q4*4+3]+=kd*v4.w;
            }
        }
        __syncthreads();
    }
    float* kvp = g_kvp + ((size_t)(blockIdx.x*64+bh))*4096 + d*64 + eb;
    #pragma unroll
    for (int j=0;j<16;j++) kvp[j] = acc[j];
    if ((t&3)==0) g_ksp[(blockIdx.x*64+bh)*64 + d] = ksa;
}

__global__ void k_kvred(){
    int i = blockIdx.x*256 + threadIdx.x;
    if (i < 64*4096){
        float s = 0.f;
        int bh = i >> 12, r = i & 4095;
        for (int c=0;c<KVCH;c++) s += g_kvp[((size_t)(c*64+bh))*4096 + r];
        g_kvf[i] = s;
    }
    if (i < 64*64){
        float s = 0.f;
        int bh = i >> 6, d = i & 63;
        for (int c=0;c<KVCH;c++) s += g_ksp[(c*64+bh)*64 + d];
        g_ks[i] = s;
    }
}

// ---------------- Mt = (kv @ Wo) transposed (4-acc) ----------------
__global__ void k_mt(const float* __restrict__ Wo){
    int idx = blockIdx.x*256 + threadIdx.x;
    if (idx >= 1048576) return;
    int b  = idx >> 16;
    int j  = (idx >> 8) & 255;
    int hd = idx & 255;
    int h = hd >> 6, d = hd & 63;
    const float* kvf = g_kvf + ((size_t)(b*4+h)*64 + d)*64;
    const float* wo  = Wo + (size_t)(h*64)*256 + j;
    float a0=0.f,a1=0.f,a2=0.f,a3=0.f;
    #pragma unroll 4
    for (int e=0; e<64; e+=4){
        a0 += kvf[e+0]*wo[(size_t)(e+0)*256];
        a1 += kvf[e+1]*wo[(size_t)(e+1)*256];
        a2 += kvf[e+2]*wo[(size_t)(e+2)*256];
        a3 += kvf[e+3]*wo[(size_t)(e+3)*256];
    }
    wsph(g_mth, g_mtl, ((size_t)b*256 + j)*256 + hd, ((a0+a1)+(a2+a3))*S_OP);
}

// ---------------- qf (z folded, scaled S_QF), split ----------------
__global__ void k_qf(){
    int gw = blockIdx.x*8 + (threadIdx.x>>5);
    int lane = threadIdx.x & 31;
    if (gw >= MROWS*4) return;
    int row = gw >> 2, h = gw & 3;
    int n = row % NSEQ, b = row / NSEQ;
    const float* base = g_qkv + (size_t)row*768 + h*64;
    float x1 = base[2*lane], x2 = base[2*lane+1];
    float c = g_cos[n*32+lane], s = g_sin[n*32+lane];
    float q1 = elu1(x1*c - x2*s);
    float q2 = elu1(x1*s + x2*c);
    const float* ks = g_ks + (b*4+h)*64;
    float pd = q1*ks[2*lane] + q2*ks[2*lane+1];
    #pragma unroll
    for (int o=16;o;o>>=1) pd += __shfl_xor_sync(0xffffffffu, pd, o);
    float z = S_QF/(pd + 1e-6f);
    size_t o0 = (size_t)row*256 + h*64 + 2*lane;
    wsph(g_qfh, g_qfl, o0,   q1*z);
    wsph(g_qfh, g_qfl, o0+1, q2*z);
}

// ---------------- write projections (exact fp32 SIMT) ----------------
__global__ void k_wproj(const float* __restrict__ Wwk, const float* __restrict__ Wwv){
    int idx = blockIdx.x*256 + threadIdx.x;   // 16*64*256
    if (idx >= 262144) return;
    int b  = idx >> 14;
    int m  = (idx >> 8) & 63;
    int jj = idx & 255;
    const float* hrow = g_h + ((size_t)(b*NSEQ) + (NSEQ-64) + m)*256;
    const float* wp = (jj < 128) ? (Wwk + jj) : (Wwv + (jj-128));
    float a0=0.f,a1=0.f,a2=0.f,a3=0.f;
    #pragma unroll 8
    for (int dd=0; dd<256; dd+=4){
        a0 += hrow[dd+0]*wp[(dd+0)*128];
        a1 += hrow[dd+1]*wp[(dd+1)*128];
        a2 += hrow[dd+2]*wp[(dd+2)*128];
        a3 += hrow[dd+3]*wp[(dd+3)*128];
    }
    float a = (a0+a1)+(a2+a3);
    if (jj < 128) g_wk[b*8192 + m*128 + jj]       = a;
    else          g_wv[b*8192 + m*128 + (jj-128)] = a;
}

// ---------------- cache write ----------------
__global__ void k_write(const float* __restrict__ Wwg, const float* __restrict__ bwg,
                        int l, int it, int pas){
    int b = blockIdx.x >> 4, k = blockIdx.x & 15;
    int t = threadIdx.x;
    __shared__ float sq[128], nc[128], sc[64], red[4];
    __shared__ float wg_s;
    float* crow = g_cache + ((size_t)(b*48 + l*16 + k))*DSLOT;
    sq[t] = crow[t];
    __syncthreads();
    if (t < 64){
        const float* wkp = g_wk + b*8192 + t*128;
        float s = 0.f;
        for (int d2=0; d2<128; d2++) s += sq[d2]*wkp[d2];
        sc[t] = s * INV_SQRT_DC;
    }
    __syncthreads();
    if (t == 0){
        float mx = sc[0];
        for (int m=1;m<64;m++) mx = fmaxf(mx, sc[m]);
        float su = 0.f;
        for (int m=0;m<64;m++){ float e = expf(sc[m]-mx); sc[m]=e; su+=e; }
        float inv = 1.f/su;
        for (int m=0;m<64;m++) sc[m] *= inv;
    }
    __syncthreads();
    float acc = 0.f;
    for (int m=0;m<64;m++) acc += sc[m]*g_wv[b*8192 + m*128 + t];
    nc[t] = acc;
    float pg = sq[t]*Wwg[l*256 + t] + acc*Wwg[l*256 + 128 + t];
    #pragma unroll
    for (int o=16;o;o>>=1) pg += __shfl_down_sync(0xffffffffu, pg, o);
    if ((t&31)==0) red[t>>5] = pg;
    __syncthreads();
    if (t==0) wg_s = sigm(red[0]+red[1]+red[2]+red[3] + bwg[l]);
    __syncthreads();
    float wg = wg_s;
    crow[t] = sq[t] + wg*nc[t];
    if (t == 0) crow[128] = wg;
    if (t < 4){
        crow[137+t] = (t==it)  ? 1.f : 0.f;
        crow[141+t] = (t==pas) ? 1.f : 0.f;
    }
}

// ---------------- feedback ----------------
__global__ void k_fbprep(const float* __restrict__ pae){
    int row = blockIdx.x, t = threadIdx.x;
    int b = row/900, s2 = row%900;
    const float* lg = g_logits + row*16;
    float mx = lg[0]; int am = 0;
    #pragma unroll
    for (int v2=1; v2<16; v2++){ float x = lg[v2]; if (x > mx){ mx=x; am=v2; } }
    float tr = g_cur[((size_t)(b*NSEQ) + TSq + s2)*256 + t];
    float pe = pae[am*256 + t];
    size_t o = (size_t)row*512;
    g_fbin[o + t]       = tr;
    g_fbin[o + 256 + t] = pe;
    wsph(g_fbih, g_fbil, o + t,       tr*S_OP);
    wsph(g_fbih, g_fbil, o + 256 + t, pe*S_OP);
}

__global__ void k_fbapply(const float* __restrict__ bfb){
    size_t i = (size_t)blockIdx.x*256 + threadIdx.x;
    int row = (int)(i>>8), t = (int)(i&255);
    float g = sigm(g_fbout[i] + bfb[t]);
    int b = row/900, s2 = row%900;
    float tr = g_fbin[(size_t)row*512+t];
    float pe = g_fbin[(size_t)row*512+256+t];
    g_cur[((size_t)(b*NSEQ) + TSq + s2)*256 + t] = tr + g*pe;
}

// ---------------- output logits ----------------
__global__ void k_logits(const float* __restrict__ Wout, const float* __restrict__ bout,
                         float* __restrict__ out){
    int t = threadIdx.x;
    int rl = t >> 4, v2 = t & 15;
    int row = blockIdx.x*16 + rl;
    int b = row/900, s2 = row%900;
    const float* hr = g_h + ((size_t)(b*NSEQ) + TSq + s2)*256;
    float a = bout[v2];
    for (int d2=0; d2<256; d2++) a += hr[d2]*Wout[d2*16 + v2];
    out[(size_t)row*16 + v2] = a;
}

// ---------------- host ----------------
static void gemm_h(const hf* Ah, const hf* Al, const hf* Bh, const hf* Bl,
                   float* C, hf* Ch, hf* Cl,
                   int M, int N, int K, int lda, int ldb, int ldc,
                   int batches, int bdiv,
                   long sA1, long sA2, long sB1, long sB2, long sC1, long sC2,
                   int flags, float alpha){
    dim3 g(N/64, (M+127)/128, batches);
    k_gemm_h<<<g,256,4*STGB>>>(Ah,Al,Bh,Bl,C,Ch,Cl,M,K,lda,ldb,ldc,
                               bdiv,sA1,sA2,sB1,sB2,sC1,sC2,flags,alpha);
}

extern "C" void kernel_launch(void* const* d_in, const int* in_sizes, int n_in,
                              void* d_out, int out_size){
    const int*   di   = (const int*)d_in[0];
    const int*   dou  = (const int*)d_in[1];
    const int*   ti   = (const int*)d_in[2];
    const float* tok  = (const float*)d_in[3];
    const float* seg  = (const float*)d_in[4];
    const float* se   = (const float*)d_in[5];
    const float* lid  = (const float*)d_in[6];
    const float* Wq   = (const float*)d_in[7];
    const float* Wkr  = (const float*)d_in[8];
    const float* Wvr  = (const float*)d_in[9];
    const float* Wg   = (const float*)d_in[10];
    const float* bg   = (const float*)d_in[11];
    const float* Wqkv = (const float*)d_in[12];
    const float* Wo   = (const float*)d_in[13];
    const float* Wwk  = (const float*)d_in[14];
    const float* Wwv  = (const float*)d_in[15];
    const float* Wwg  = (const float*)d_in[16];
    const float* bwg  = (const float*)d_in[17];
    const float* Wout = (const float*)d_in[18];
    const float* bout = (const float*)d_in[19];
    const float* pae  = (const float*)d_in[20];
    const float* Wfb  = (const float*)d_in[21];
    const float* bfb  = (const float*)d_in[22];

    cudaFuncSetAttribute(k_gemm_h, cudaFuncAttributeMaxDynamicSharedMemorySize, 4*STGB);

    float *gh, *gsc, *gqkv, *gfbo, *glg;
    hf *ghh,*ghl,*gsch,*gscl,*gqfh,*gqfl,*gfbih,*gfbil;
    hf *gkqh,*gkql,*gvch,*gvcl,*gmth,*gmtl;
    hf *wqkvh,*wqkvl,*wfbh,*wfbl;
    cudaGetSymbolAddress((void**)&gh,   g_h);
    cudaGetSymbolAddress((void**)&gsc,  g_sc);
    cudaGetSymbolAddress((void**)&gqkv, g_qkv);
    cudaGetSymbolAddress((void**)&gfbo, g_fbout);
    cudaGetSymbolAddress((void**)&glg,  g_logits);
    cudaGetSymbolAddress((void**)&ghh,  g_hh);
    cudaGetSymbolAddress((void**)&ghl,  g_hl);
    cudaGetSymbolAddress((void**)&gsch, g_sch);
    cudaGetSymbolAddress((void**)&gscl, g_scl);
    cudaGetSymbolAddress((void**)&gqfh, g_qfh);
    cudaGetSymbolAddress((void**)&gqfl, g_qfl);
    cudaGetSymbolAddress((void**)&gfbih,g_fbih);
    cudaGetSymbolAddress((void**)&gfbil,g_fbil);
    cudaGetSymbolAddress((void**)&gkqh, g_kqh);
    cudaGetSymbolAddress((void**)&gkql, g_kql);
    cudaGetSymbolAddress((void**)&gvch, g_vch);
    cudaGetSymbolAddress((void**)&gvcl, g_vcl);
    cudaGetSymbolAddress((void**)&gmth, g_mth);
    cudaGetSymbolAddress((void**)&gmtl, g_mtl);
    cudaGetSymbolAddress((void**)&wqkvh,g_wqkvh);
    cudaGetSymbolAddress((void**)&wqkvl,g_wqkvl);
    cudaGetSymbolAddress((void**)&wfbh, g_wfbh);
    cudaGetSymbolAddress((void**)&wfbl, g_wfbl);

    const float A12 = 1.f/4096.f;
    const float AQM = 1.f/33554432.f;

    k_init<<<(NSEQ*32+255)/256,256>>>(se, lid);
    k_embed<<<dim3(NSEQ,BBn),256>>>(di, dou, ti, tok, seg);
    k_copy<<<(MROWS*DD/4)/256,256>>>();

    bool prefix_done = false;
    for (int pas=0; pas<2; pas++){
        if (pas > 0){
            k_fbprep<<<FBROWS,256>>>(pae);
            gemm_h(gfbih, gfbil, wfbh, wfbl, gfbo, 0, 0,
                   FBROWS, 256, 512, 512, 512, 256,
                   1,1, 0,0, 0,0, 0,0, 1, A12);
            k_fbapply<<<(FBROWS*256)/256,256>>>(bfb);
            k_copy<<<(MROWS*DD/4)/256,256>>>();
        }
        for (int l=0; l<LL; l++){
            for (int it=0; it<2; it++){
                k_cachekv<<<(BBn*22528+255)/256,256>>>(Wkr + (size_t)l*DSLOT*128,
                                                       Wvr + (size_t)l*DSLOT*256);
                k_kq<<<262144/256,256>>>(Wq + (size_t)l*256*128);
                gemm_h(ghh, ghl, gkqh, gkql, gsc, 0, 0,
                       NSEQ, 64, 256, 256, 256, 64,
                       BBn,1, (long)NSEQ*256,0, 64*256,0, (long)NSEQ*64,0, 1, A12);
                if (!prefix_done){
                    k_wsplit_all<<<(720896+255)/256,256>>>(Wqkv, Wfb);
                    prefix_done = true;
                }
                k_softrg<<<MROWS/8,256>>>(Wg, bg, l);
                gemm_h(gsch, gscl, gvch, gvcl, gh, ghh, ghl,
                       NSEQ, 256, 64, 64, 64, 256,
                       BBn,1, (long)NSEQ*64,0, 16384,0, (long)NSEQ*256,0, 7, 1.f/65536.f);
                gemm_h(ghh, ghl, wqkvh + (size_t)l*768*256, wqkvl + (size_t)l*768*256,
                       gqkv, 0, 0, MROWS, 768, 256, 256, 256, 768,
                       1,1, 0,0, 0,0, 0,0, 1, A12);
                k_kvacc<<<dim3(KVCH,64),256>>>();
                k_kvred<<<1024,256>>>();
                k_mt<<<1048576/256,256>>>(Wo + (size_t)l*256*256);
                k_qf<<<(MROWS*4)/8,256>>>();
                gemm_h(gqfh, gqfl, gmth, gmtl, gh, ghh, ghl,
                       NSEQ, 256, 256, 256, 256, 256,
                       BBn,1, (long)NSEQ*256,0, 65536,0, (long)NSEQ*256,0, 7, AQM);
                k_wproj<<<262144/256,256>>>(Wwk + (size_t)l*256*128,
                                            Wwv + (size_t)l*256*128);
                k_write<<<BBn*16,128>>>(Wwg, bwg, l, it, pas);
            }
        }
        if (pas == 0) k_logits<<<FBROWS/16,256>>>(Wout, bout, glg);
        else          k_logits<<<FBROWS/16,256>>>(Wout, bout, (float*)d_out);
    }
}

// round 11
// speedup vs baseline: 1.0643x; 1.0643x over previous
#include <cuda_runtime.h>
#include <cuda_fp16.h>
#include <cstdint>
#include <cstddef>

#define DD     256
#define LL     3
#define NSEQ   6300
#define TSq    5400
#define BBn    16
#define MROWS  (BBn*NSEQ)
#define FBROWS (BBn*900)
#define DSLOT  145
#define INV_SQRT_DC 0.08838834764831843f
#define S_OP  64.0f
#define S_SC  1024.0f
#define S_QF  524288.0f
#define KVCH  32

typedef __half hf;

// ---------------- fp32 scratch ----------------
__device__ __align__(16) float g_cur [(size_t)MROWS*DD];
__device__ __align__(16) float g_h   [(size_t)MROWS*DD];
__device__ __align__(16) float g_sc  [(size_t)MROWS*64];
__device__ __align__(16) float g_qkv [(size_t)MROWS*768];
__device__ __align__(16) float g_cache[BBn*48*DSLOT];
__device__ __align__(16) float g_ks  [64*64];
__device__ __align__(16) float g_kvp [(size_t)KVCH*64*4096];
__device__ __align__(16) float g_ksp [KVCH*64*64];
__device__ __align__(16) float g_kvf [64*4096];
__device__ __align__(16) float g_wqk [3*DSLOT*256];
__device__ __align__(16) float g_wk  [BBn*64*128];
__device__ __align__(16) float g_wv  [BBn*64*128];
__device__ __align__(16) float g_cos [NSEQ*32];
__device__ __align__(16) float g_sin [NSEQ*32];
__device__ __align__(16) float g_logits[FBROWS*16];
__device__ __align__(16) float g_fbin [(size_t)FBROWS*512];
__device__ __align__(16) float g_fbout[(size_t)FBROWS*256];

// ---------------- fp16 hi/lo splits (scaled) ----------------
__device__ __align__(16) hf g_hh [(size_t)MROWS*256];
__device__ __align__(16) hf g_hl [(size_t)MROWS*256];
__device__ __align__(16) hf g_sch[(size_t)MROWS*64];
__device__ __align__(16) hf g_scl[(size_t)MROWS*64];
__device__ __align__(16) hf g_qfh[(size_t)MROWS*256];
__device__ __align__(16) hf g_qfl[(size_t)MROWS*256];
__device__ __align__(16) hf g_fbih[(size_t)FBROWS*512];
__device__ __align__(16) hf g_fbil[(size_t)FBROWS*512];
__device__ __align__(16) hf g_kqh[16*64*256],  g_kql[16*64*256];   // [b][m64][d256]
__device__ __align__(16) hf g_vch[16*256*64],  g_vcl[16*256*64];   // [b][j256][m64]
__device__ __align__(16) hf g_mth[16*256*256], g_mtl[16*256*256];  // [b][j256][hd256]
__device__ __align__(16) hf g_wqkvh[3*768*256],g_wqkvl[3*768*256];
__device__ __align__(16) hf g_wfbh[256*512],   g_wfbl[256*512];

__device__ __forceinline__ float sigm(float x){ return 1.f/(1.f+expf(-x)); }
__device__ __forceinline__ float elu1(float x){ return x>0.f ? x+1.f : expf(x); }

__device__ __forceinline__ void wsph(hf* ph, hf* pl, size_t i, float x){
    hf h = __float2half_rn(x);
    ph[i] = h;
    pl[i] = __float2half_rn(x - __half2float(h));
}

// ---------------- init ----------------
__global__ void k_init(const float* __restrict__ se, const float* __restrict__ lid){
    int i = blockIdx.x*256 + threadIdx.x;
    if (i < NSEQ*32){
        int n = i/32, j = i%32;
        float inv = 1.f/powf(10000.f, (float)(2*j)/64.f);
        float f = (float)n * inv;
        g_cos[i] = cosf(f);
        g_sin[i] = sinf(f);
    }
    if (i < BBn*48*DSLOT){
        int r2 = i % (48*DSLOT);
        int slot = r2 / DSLOT, c = r2 % DSLOT;
        float v = 0.f;
        if (c < 128)                  v = se[slot*128 + c];
        else if (c >= 129 && c < 137) v = lid[(slot/16)*8 + (c-129)];
        g_cache[i] = v;
    }
}

__global__ void k_embed(const int* __restrict__ di, const int* __restrict__ dou,
                        const int* __restrict__ ti, const float* __restrict__ tok,
                        const float* __restrict__ seg){
    int n = blockIdx.x, b = blockIdx.y, t = threadIdx.x;
    int tk;
    if (n < TSq){
        int d = n/1800, rem = n%1800, w = rem/900, s = rem%900;
        tk = w ? dou[(b*3+d)*900+s] : di[(b*3+d)*900+s];
    } else {
        tk = ti[b*900 + (n-TSq)];
    }
    g_cur[((size_t)b*NSEQ+n)*DD + t] = tok[tk*DD+t] + seg[t];
}

__global__ void k_copy(){
    size_t i = ((size_t)blockIdx.x*256 + threadIdx.x)*4;
    float4 v = *(const float4*)(g_cur + i);
    *(float4*)(g_h + i) = v;
    wsph(g_hh, g_hl, i+0, v.x*S_OP);
    wsph(g_hh, g_hl, i+1, v.y*S_OP);
    wsph(g_hh, g_hl, i+2, v.z*S_OP);
    wsph(g_hh, g_hl, i+3, v.w*S_OP);
}

// ---------------- prefix: WQK = Wk @ Wq^T  [l][dd145][d256] ----------------
__global__ void k_wqk(const float* __restrict__ Wk, const float* __restrict__ Wq){
    int idx = blockIdx.x*256 + threadIdx.x;       // 3*145*256 = 111360
    if (idx >= 3*DSLOT*256) return;
    int l  = idx / (DSLOT*256);
    int r  = idx % (DSLOT*256);
    int dd = r >> 8, d = r & 255;
    const float4* wk = (const float4*)(Wk + ((size_t)l*DSLOT + dd)*128);
    const float4* wq = (const float4*)(Wq + ((size_t)l*256 + d)*128);
    float a0=0.f,a1=0.f,a2=0.f,a3=0.f;
    #pragma unroll 8
    for (int c=0; c<32; c+=4){
        float4 k0=wk[c+0], q0=wq[c+0];
        float4 k1=wk[c+1], q1=wq[c+1];
        float4 k2=wk[c+2], q2=wq[c+2];
        float4 k3=wk[c+3], q3=wq[c+3];
        a0 += k0.x*q0.x + k0.y*q0.y + k0.z*q0.z + k0.w*q0.w;
        a1 += k1.x*q1.x + k1.y*q1.y + k1.z*q1.z + k1.w*q1.w;
        a2 += k2.x*q2.x + k2.y*q2.y + k2.z*q2.z + k2.w*q2.w;
        a3 += k3.x*q3.x + k3.y*q3.y + k3.z*q3.z + k3.w*q3.w;
    }
    g_wqk[idx] = (a0+a1)+(a2+a3);
}

// merged weight transpose+split (Wqkv, Wfb)
__device__ __forceinline__ void wtsplit(const float* src, hf* dh, hf* dl,
                                        int idx, int KK, int NN){
    int l = idx/(KK*NN), rem = idx%(KK*NN);
    int k = rem/NN, n = rem%NN;
    float x = src[idx]*S_OP;
    size_t o = (size_t)l*KK*NN + (size_t)n*KK + k;
    hf h = __float2half_rn(x);
    dh[o] = h;
    dl[o] = __float2half_rn(x - __half2float(h));
}

__global__ void k_wsplit_all(const float* __restrict__ Wqkv, const float* __restrict__ Wfb){
    int idx = blockIdx.x*256 + threadIdx.x;
    if (idx < 589824){ wtsplit(Wqkv, g_wqkvh, g_wqkvl, idx, 256, 768); return; }
    idx -= 589824;
    if (idx < 131072){ wtsplit(Wfb, g_wfbh, g_wfbl, idx, 512, 256); return; }
}

// ---------------- MMA helpers ----------------
__device__ __forceinline__ void mma_f32(float* c, const uint32_t* a, const uint32_t* b){
    asm volatile(
      "mma.sync.aligned.m16n8k16.row.col.f32.f16.f16.f32 "
      "{%0,%1,%2,%3},{%4,%5,%6,%7},{%8,%9},{%0,%1,%2,%3};\n"
      : "+f"(c[0]),"+f"(c[1]),"+f"(c[2]),"+f"(c[3])
      : "r"(a[0]),"r"(a[1]),"r"(a[2]),"r"(a[3]), "r"(b[0]),"r"(b[1]));
}
__device__ __forceinline__ void mma_f16(uint32_t* c, const uint32_t* a, const uint32_t* b){
    asm volatile(
      "mma.sync.aligned.m16n8k16.row.col.f16.f16.f16.f16 "
      "{%0,%1},{%2,%3,%4,%5},{%6,%7},{%0,%1};\n"
      : "+r"(c[0]),"+r"(c[1])
      : "r"(a[0]),"r"(a[1]),"r"(a[2]),"r"(a[3]), "r"(b[0]),"r"(b[1]));
}
__device__ __forceinline__ void ldsm4(uint32_t& r0,uint32_t& r1,uint32_t& r2,uint32_t& r3,
                                      uint32_t addr){
    asm volatile("ldmatrix.sync.aligned.m8n8.x4.shared.b16 {%0,%1,%2,%3}, [%4];\n"
        : "=r"(r0),"=r"(r1),"=r"(r2),"=r"(r3) : "r"(addr));
}

// ---------------- fp16 3-term GEMM, 4-stage pipeline, 2 CTAs/SM ----------------
#define STGB 18432
__global__ void __launch_bounds__(256,2) k_gemm_h(
    const hf* __restrict__ Ah, const hf* __restrict__ Al,
    const hf* __restrict__ Bh, const hf* __restrict__ Bl,
    float* C, hf* Ch, hf* Cl,
    int M, int K, int lda, int ldb, int ldc,
    int bdiv, long sA1, long sA2, long sB1, long sB2, long sC1, long sC2,
    int flags, float alpha)
{
    extern __shared__ __align__(16) char smem_raw[];
    uint32_t smem_u32 = (uint32_t)__cvta_generic_to_shared(smem_raw);

    int bz = blockIdx.z;
    int b1 = bz / bdiv, b2 = bz % bdiv;
    Ah += (size_t)b1*sA1 + (size_t)b2*sA2;
    Al += (size_t)b1*sA1 + (size_t)b2*sA2;
    Bh += (size_t)b1*sB1 + (size_t)b2*sB2;
    Bl += (size_t)b1*sB1 + (size_t)b2*sB2;
    size_t coff = (size_t)b1*sC1 + (size_t)b2*sC2;

    const int t = threadIdx.x;
    const int lane = t & 31, wid = t >> 5;
    const int g = lane >> 2, t4 = lane & 3;
    const int wm = wid & 3, wn = wid >> 2;
    const int row0 = blockIdx.y*128;
    const int col0 = blockIdx.x*64;

    const int sel = lane >> 3, rr = lane & 7;
    const int aoff = (wm*32 + (sel&1)*8 + rr)*48 + ((sel>>1)*8)*2;
    const int boff = (wn*32 + (sel>>1)*8 + rr)*48 + ((sel&1)*8)*2;

    float    acc[2][4][4];
    uint32_t acl[2][4][2];
    #pragma unroll
    for (int i=0;i<2;i++)
        #pragma unroll
        for (int j=0;j<4;j++){
            #pragma unroll
            for (int q=0;q<4;q++) acc[i][j][q]=0.f;
            acl[i][j][0]=0u; acl[i][j][1]=0u;
        }

    const int nk = K >> 4;

    auto load_stage = [&](int kt, int stage){
        uint32_t sb = smem_u32 + stage*STGB;
        #pragma unroll
        for (int pass=0; pass<3; pass++){
            int c = t + pass*256;
            if (c < 512){
                int mat  = c >> 8;
                int r    = (c >> 1) & 127;
                int half = c & 1;
                bool ok = (row0 + r) < M;
                int rc = ok ? r : 0;
                const hf* src = (mat ? Al : Ah) + (size_t)(row0+rc)*lda + kt*16 + half*8;
                uint32_t dst = sb + mat*6144 + r*48 + half*16;
                int sz = ok ? 16 : 0;
                asm volatile("cp.async.ca.shared.global [%0], [%1], 16, %2;\n"
                             :: "r"(dst), "l"(src), "r"(sz));
            } else {
                int c2 = c - 512;
                int bmat = c2 >> 7;
                int rem  = c2 & 127;
                int r = rem >> 1, half = rem & 1;
                const hf* src = (bmat ? Bl : Bh) + (size_t)(col0+r)*ldb + kt*16 + half*8;
                uint32_t dst = sb + 12288 + bmat*3072 + r*48 + half*16;
                asm volatile("cp.async.ca.shared.global [%0], [%1], 16, 16;\n"
                             :: "r"(dst), "l"(src));
            }
        }
    };

    #pragma unroll
    for (int p=0; p<3; p++){
        if (p < nk) load_stage(p, p);
        asm volatile("cp.async.commit_group;\n");
    }

    for (int kt=0; kt<nk; kt++){
        asm volatile("cp.async.wait_group 2;\n");
        __syncthreads();
        int kn = kt + 3;
        if (kn < nk) load_stage(kn, kn & 3);
        asm volatile("cp.async.commit_group;\n");

        uint32_t sb = smem_u32 + (kt & 3)*STGB;
        uint32_t ah[2][4], al_[2][4], bh_[4][2], bl_[4][2];
        #pragma unroll
        for (int mt=0; mt<2; mt++){
            ldsm4(ah[mt][0],ah[mt][1],ah[mt][2],ah[mt][3],     sb + aoff + mt*768);
            ldsm4(al_[mt][0],al_[mt][1],al_[mt][2],al_[mt][3], sb + 6144 + aoff + mt*768);
        }
        #pragma unroll
        for (int ntp=0; ntp<2; ntp++){
            uint32_t r0,r1,r2,r3;
            ldsm4(r0,r1,r2,r3, sb + 12288 + boff + ntp*768);
            bh_[2*ntp][0]=r0; bh_[2*ntp][1]=r1; bh_[2*ntp+1][0]=r2; bh_[2*ntp+1][1]=r3;
            ldsm4(r0,r1,r2,r3, sb + 15360 + boff + ntp*768);
            bl_[2*ntp][0]=r0; bl_[2*ntp][1]=r1; bl_[2*ntp+1][0]=r2; bl_[2*ntp+1][1]=r3;
        }
        #pragma unroll
        for (int mt=0; mt<2; mt++){
            #pragma unroll
            for (int nt=0; nt<4; nt++){
                mma_f32(acc[mt][nt], ah[mt],  bh_[nt]);
                mma_f16(acl[mt][nt], ah[mt],  bl_[nt]);
                mma_f16(acl[mt][nt], al_[mt], bh_[nt]);
            }
        }
    }

    #pragma unroll
    for (int mt=0; mt<2; mt++){
        #pragma unroll
        for (int nt=0; nt<4; nt++){
            int col = col0 + wn*32 + nt*8 + t4*2;
            __half2 lo0 = *(__half2*)&acl[mt][nt][0];
            __half2 lo1 = *(__half2*)&acl[mt][nt][1];
            float cx[4];
            cx[0] = __half2float(lo0.x); cx[1] = __half2float(lo0.y);
            cx[2] = __half2float(lo1.x); cx[3] = __half2float(lo1.y);
            #pragma unroll
            for (int hrow=0; hrow<2; hrow++){
                int r = row0 + wm*32 + mt*16 + g + hrow*8;
                if (r >= M) continue;
                float x = alpha*(acc[mt][nt][hrow*2+0] + cx[hrow*2+0]);
                float y = alpha*(acc[mt][nt][hrow*2+1] + cx[hrow*2+1]);
                size_t off = coff + (size_t)r*ldc + col;
                if (flags & 2){ x += C[off]; y += C[off+1]; }
                if (flags & 1){ C[off] = x; C[off+1] = y; }
                if (flags & 4){
                    float xs = x*S_OP, ys = y*S_OP;
                    hf xh = __float2half_rn(xs);
                    hf yh = __float2half_rn(ys);
                    __half2 ph; ph.x = xh; ph.y = yh;
                    *(__half2*)(Ch + off) = ph;
                    __half2 pl;
                    pl.x = __float2half_rn(xs - __half2float(xh));
                    pl.y = __float2half_rn(ys - __half2float(yh));
                    *(__half2*)(Cl + off) = pl;
                }
            }
        }
    }
}

// ---------------- fused cache projections: KQ = cache@WQK, vc = cache@Wv ----------------
// grid (48, 16): block = (m, b). Cache row staged in smem; weight loads coalesced.
// Rows m in [48,64) of g_kq* / columns m of g_vc* stay zero (.bss, never written).
__global__ void k_cachekq(const float* __restrict__ WQK, const float* __restrict__ Wv){
    __shared__ float row[DSLOT];
    int m = blockIdx.x, b = blockIdx.y;
    int t = threadIdx.x;
    const float* cr = g_cache + ((size_t)(b*48) + m)*DSLOT;
    if (t < DSLOT) row[t] = cr[t];
    __syncthreads();
    float a0=0.f, a1=0.f, a2=0.f, a3=0.f;   // a0/a1: KQ even/odd; a2/a3: vc even/odd
    #pragma unroll 2
    for (int dd=0; dd<144; dd+=2){
        float r0 = row[dd], r1 = row[dd+1];
        a0 += r0*WQK[(size_t)dd*256 + t];
        a1 += r1*WQK[(size_t)(dd+1)*256 + t];
        a2 += r0*Wv[(size_t)dd*256 + t];
        a3 += r1*Wv[(size_t)(dd+1)*256 + t];
    }
    float r144 = row[144];
    float kq = (a0+a1) + r144*WQK[(size_t)144*256 + t];
    float vc = (a2+a3) + r144*Wv[(size_t)144*256 + t];
    wsph(g_kqh, g_kql, ((size_t)b*64 + m)*256 + t, kq*S_OP);
    wsph(g_vch, g_vcl, (size_t)b*16384 + (size_t)t*64 + m, vc*S_OP);
}

// ---------------- softmax + rgate fold ----------------
__global__ void k_softrg(const float* __restrict__ Wg, const float* __restrict__ bg, int l){
    int gw = blockIdx.x*8 + (threadIdx.x>>5);
    int lane = threadIdx.x & 31;
    if (gw >= MROWS) return;
    const float* hrow = g_h + (size_t)gw*256;
    const float* wg = Wg + l*256;
    float pg = 0.f;
    #pragma unroll
    for (int j=0;j<8;j++) pg += hrow[lane + 32*j]*wg[lane + 32*j];
    #pragma unroll
    for (int o=16;o;o>>=1) pg += __shfl_xor_sync(0xffffffffu, pg, o);
    float rgate = sigm(pg + bg[l]);
    const float* scp = g_sc + (size_t)gw*64;
    float s0 = scp[lane]*INV_SQRT_DC;
    float s1 = (lane<16) ? scp[lane+32]*INV_SQRT_DC : -1e30f;
    float mx = fmaxf(s0, s1);
    #pragma unroll
    for (int o=16;o;o>>=1) mx = fmaxf(mx, __shfl_xor_sync(0xffffffffu, mx, o));
    float e0 = expf(s0-mx);
    float e1 = (lane<16) ? expf(s1-mx) : 0.f;
    float su = e0+e1;
    #pragma unroll
    for (int o=16;o;o>>=1) su += __shfl_xor_sync(0xffffffffu, su, o);
    float sc = rgate*S_SC/su;
    wsph(g_sch, g_scl, (size_t)gw*64 + lane, e0*sc);
    wsph(g_sch, g_scl, (size_t)gw*64 + lane + 32, (lane<16) ? e1*sc : 0.f);
}

// ---------------- linear attention: kv / ksum partials ----------------
__global__ void __launch_bounds__(256) k_kvacc(){
    int bh = blockIdx.y;
    int b = bh >> 2, h = bh & 3;
    int n0 = blockIdx.x*200;
    __shared__ float kf[4*64];
    __shared__ float vh[4*64];
    int t = threadIdx.x;
    int d = t >> 2, eb = (t & 3) << 4;
    float acc[16];
    #pragma unroll
    for (int j=0;j<16;j++) acc[j]=0.f;
    float ksa = 0.f;
    for (int nb=0; nb<200; nb+=4){
        int nbase = n0 + nb;
        if (t < 128){
            int sub = t>>5, i2 = t&31;
            int n = nbase + sub;
            float v1=0.f, v2=0.f;
            if (n < NSEQ){
                const float* bp = g_qkv + (size_t)(b*NSEQ+n)*768 + 256 + h*64;
                float x1=bp[2*i2], x2=bp[2*i2+1];
                float c=g_cos[n*32+i2], s=g_sin[n*32+i2];
                v1 = elu1(x1*c - x2*s);
                v2 = elu1(x1*s + x2*c);
            }
            kf[sub*64+2*i2]=v1; kf[sub*64+2*i2+1]=v2;
        } else {
            int t2 = t-128;
            #pragma unroll
            for (int q2=0;q2<2;q2++){
                int idx = t2 + q2*128;
                int sub = idx>>6, j = idx&63;
                int n = nbase + sub;
                vh[sub*64+j] = (n<NSEQ) ? g_qkv[(size_t)(b*NSEQ+n)*768 + 512 + h*64 + j] : 0.f;
            }
        }
        __syncthreads();
        #pragma unroll
        for (int sub=0; sub<4; sub++){
            float kd = kf[sub*64+d];
            ksa += kd;
            const float4* vp = (const float4*)&vh[sub*64+eb];
            #pragma unroll
            for (int q4=0;q4<4;q4++){
                float4 v4 = vp[q4];
                acc[q4*4+0]+=kd*v4.x; acc[q4*4+1]+=kd*v4.y;
                acc[q4*4+2]+=kd*v4.z; acc[q4*4+3]+=kd*v4.w;
            }
        }
        __syncthreads();
    }
    float* kvp = g_kvp + ((size_t)(blockIdx.x*64+bh))*4096 + d*64 + eb;
    #pragma unroll
    for (int j=0;j<16;j++) kvp[j] = acc[j];
    if ((t&3)==0) g_ksp[(blockIdx.x*64+bh)*64 + d] = ksa;
}

__global__ void k_kvred(){
    int i = blockIdx.x*256 + threadIdx.x;
    if (i < 64*4096){
        float s = 0.f;
        int bh = i >> 12, r = i & 4095;
        for (int c=0;c<KVCH;c++) s += g_kvp[((size_t)(c*64+bh))*4096 + r];
        g_kvf[i] = s;
    }
    if (i < 64*64){
        float s = 0.f;
        int bh = i >> 6, d = i & 63;
        for (int c=0;c<KVCH;c++) s += g_ksp[(c*64+bh)*64 + d];
        g_ks[i] = s;
    }
}

// ---------------- merged Mt + qf (both depend only on kvred) ----------------
// blocks [0,4096): Mt; blocks [4096, 4096+50400): qf
#define MT_BLOCKS 4096
#define QF_BLOCKS ((MROWS*4)/8)
__global__ void k_mtqf(const float* __restrict__ Wo){
    if (blockIdx.x < MT_BLOCKS){
        // Mt: thread group = (b, hd); j innermost -> coalesced wo loads, kvf broadcast
        int idx = blockIdx.x*256 + threadIdx.x;
        int b  = idx >> 16;
        int hd = (idx >> 8) & 255;
        int j  = idx & 255;
        int h = hd >> 6, d = hd & 63;
        const float* kvf = g_kvf + ((size_t)(b*4+h)*64 + d)*64;
        const float* wo  = Wo + (size_t)(h*64)*256 + j;
        float a0=0.f,a1=0.f,a2=0.f,a3=0.f;
        #pragma unroll 4
        for (int e=0; e<64; e+=4){
            a0 += kvf[e+0]*wo[(size_t)(e+0)*256];
            a1 += kvf[e+1]*wo[(size_t)(e+1)*256];
            a2 += kvf[e+2]*wo[(size_t)(e+2)*256];
            a3 += kvf[e+3]*wo[(size_t)(e+3)*256];
        }
        wsph(g_mth, g_mtl, ((size_t)b*256 + j)*256 + hd, ((a0+a1)+(a2+a3))*S_OP);
    } else {
        int gw = (blockIdx.x - MT_BLOCKS)*8 + (threadIdx.x>>5);
        int lane = threadIdx.x & 31;
        if (gw >= MROWS*4) return;
        int row = gw >> 2, h = gw & 3;
        int n = row % NSEQ, b = row / NSEQ;
        const float* base = g_qkv + (size_t)row*768 + h*64;
        float x1 = base[2*lane], x2 = base[2*lane+1];
        float c = g_cos[n*32+lane], s = g_sin[n*32+lane];
        float q1 = elu1(x1*c - x2*s);
        float q2 = elu1(x1*s + x2*c);
        const float* ks = g_ks + (b*4+h)*64;
        float pd = q1*ks[2*lane] + q2*ks[2*lane+1];
        #pragma unroll
        for (int o=16;o;o>>=1) pd += __shfl_xor_sync(0xffffffffu, pd, o);
        float z = S_QF/(pd + 1e-6f);
        size_t o0 = (size_t)row*256 + h*64 + 2*lane;
        wsph(g_qfh, g_qfl, o0,   q1*z);
        wsph(g_qfh, g_qfl, o0+1, q2*z);
    }
}

// ---------------- write projections (exact fp32) ----------------
__global__ void k_wproj(const float* __restrict__ Wwk, const float* __restrict__ Wwv){
    int idx = blockIdx.x*256 + threadIdx.x;
    if (idx >= 262144) return;
    int b  = idx >> 14;
    int m  = (idx >> 8) & 63;
    int jj = idx & 255;
    const float* hrow = g_h + ((size_t)(b*NSEQ) + (NSEQ-64) + m)*256;
    const float* wp = (jj < 128) ? (Wwk + jj) : (Wwv + (jj-128));
    float a0=0.f,a1=0.f,a2=0.f,a3=0.f;
    #pragma unroll 8
    for (int dd=0; dd<256; dd+=4){
        a0 += hrow[dd+0]*wp[(dd+0)*128];
        a1 += hrow[dd+1]*wp[(dd+1)*128];
        a2 += hrow[dd+2]*wp[(dd+2)*128];
        a3 += hrow[dd+3]*wp[(dd+3)*128];
    }
    float a = (a0+a1)+(a2+a3);
    if (jj < 128) g_wk[b*8192 + m*128 + jj]       = a;
    else          g_wv[b*8192 + m*128 + (jj-128)] = a;
}

// ---------------- cache write ----------------
__global__ void k_write(const float* __restrict__ Wwg, const float* __restrict__ bwg,
                        int l, int it, int pas){
    int b = blockIdx.x >> 4, k = blockIdx.x & 15;
    int t = threadIdx.x;
    __shared__ float sq[128], nc[128], sc[64], red[4];
    __shared__ float wg_s;
    float* crow = g_cache + ((size_t)(b*48 + l*16 + k))*DSLOT;
    sq[t] = crow[t];
    __syncthreads();
    if (t < 64){
        const float* wkp = g_wk + b*8192 + t*128;
        float s = 0.f;
        for (int d2=0; d2<128; d2++) s += sq[d2]*wkp[d2];
        sc[t] = s * INV_SQRT_DC;
    }
    __syncthreads();
    if (t == 0){
        float mx = sc[0];
        for (int m=1;m<64;m++) mx = fmaxf(mx, sc[m]);
        float su = 0.f;
        for (int m=0;m<64;m++){ float e = expf(sc[m]-mx); sc[m]=e; su+=e; }
        float inv = 1.f/su;
        for (int m=0;m<64;m++) sc[m] *= inv;
    }
    __syncthreads();
    float acc = 0.f;
    for (int m=0;m<64;m++) acc += sc[m]*g_wv[b*8192 + m*128 + t];
    nc[t] = acc;
    float pg = sq[t]*Wwg[l*256 + t] + acc*Wwg[l*256 + 128 + t];
    #pragma unroll
    for (int o=16;o;o>>=1) pg += __shfl_down_sync(0xffffffffu, pg, o);
    if ((t&31)==0) red[t>>5] = pg;
    __syncthreads();
    if (t==0) wg_s = sigm(red[0]+red[1]+red[2]+red[3] + bwg[l]);
    __syncthreads();
    float wg = wg_s;
    crow[t] = sq[t] + wg*nc[t];
    if (t == 0) crow[128] = wg;
    if (t < 4){
        crow[137+t] = (t==it)  ? 1.f : 0.f;
        crow[141+t] = (t==pas) ? 1.f : 0.f;
    }
}

// ---------------- feedback ----------------
__global__ void k_fbprep(const float* __restrict__ pae){
    int row = blockIdx.x, t = threadIdx.x;
    int b = row/900, s2 = row%900;
    const float* lg = g_logits + row*16;
    float mx = lg[0]; int am = 0;
    #pragma unroll
    for (int v2=1; v2<16; v2++){ float x = lg[v2]; if (x > mx){ mx=x; am=v2; } }
    float tr = g_cur[((size_t)(b*NSEQ) + TSq + s2)*256 + t];
    float pe = pae[am*256 + t];
    size_t o = (size_t)row*512;
    g_fbin[o + t]       = tr;
    g_fbin[o + 256 + t] = pe;
    wsph(g_fbih, g_fbil, o + t,       tr*S_OP);
    wsph(g_fbih, g_fbil, o + 256 + t, pe*S_OP);
}

__global__ void k_fbapply(const float* __restrict__ bfb){
    size_t i = (size_t)blockIdx.x*256 + threadIdx.x;
    int row = (int)(i>>8), t = (int)(i&255);
    float g = sigm(g_fbout[i] + bfb[t]);
    int b = row/900, s2 = row%900;
    float tr = g_fbin[(size_t)row*512+t];
    float pe = g_fbin[(size_t)row*512+256+t];
    g_cur[((size_t)(b*NSEQ) + TSq + s2)*256 + t] = tr + g*pe;
}

// ---------------- output logits ----------------
__global__ void k_logits(const float* __restrict__ Wout, const float* __restrict__ bout,
                         float* __restrict__ out){
    int t = threadIdx.x;
    int rl = t >> 4, v2 = t & 15;
    int row = blockIdx.x*16 + rl;
    int b = row/900, s2 = row%900;
    const float* hr = g_h + ((size_t)(b*NSEQ) + TSq + s2)*256;
    float a = bout[v2];
    for (int d2=0; d2<256; d2++) a += hr[d2]*Wout[d2*16 + v2];
    out[(size_t)row*16 + v2] = a;
}

// ---------------- host ----------------
static void gemm_h(const hf* Ah, const hf* Al, const hf* Bh, const hf* Bl,
                   float* C, hf* Ch, hf* Cl,
                   int M, int N, int K, int lda, int ldb, int ldc,
                   int batches, int bdiv,
                   long sA1, long sA2, long sB1, long sB2, long sC1, long sC2,
                   int flags, float alpha){
    dim3 g(N/64, (M+127)/128, batches);
    k_gemm_h<<<g,256,4*STGB>>>(Ah,Al,Bh,Bl,C,Ch,Cl,M,K,lda,ldb,ldc,
                               bdiv,sA1,sA2,sB1,sB2,sC1,sC2,flags,alpha);
}

extern "C" void kernel_launch(void* const* d_in, const int* in_sizes, int n_in,
                              void* d_out, int out_size){
    const int*   di   = (const int*)d_in[0];
    const int*   dou  = (const int*)d_in[1];
    const int*   ti   = (const int*)d_in[2];
    const float* tok  = (const float*)d_in[3];
    const float* seg  = (const float*)d_in[4];
    const float* se   = (const float*)d_in[5];
    const float* lid  = (const float*)d_in[6];
    const float* Wq   = (const float*)d_in[7];
    const float* Wkr  = (const float*)d_in[8];
    const float* Wvr  = (const float*)d_in[9];
    const float* Wg   = (const float*)d_in[10];
    const float* bg   = (const float*)d_in[11];
    const float* Wqkv = (const float*)d_in[12];
    const float* Wo   = (const float*)d_in[13];
    const float* Wwk  = (const float*)d_in[14];
    const float* Wwv  = (const float*)d_in[15];
    const float* Wwg  = (const float*)d_in[16];
    const float* bwg  = (const float*)d_in[17];
    const float* Wout = (const float*)d_in[18];
    const float* bout = (const float*)d_in[19];
    const float* pae  = (const float*)d_in[20];
    const float* Wfb  = (const float*)d_in[21];
    const float* bfb  = (const float*)d_in[22];

    cudaFuncSetAttribute(k_gemm_h, cudaFuncAttributeMaxDynamicSharedMemorySize, 4*STGB);

    float *gh, *gsc, *gqkv, *gfbo, *glg, *gwqk;
    hf *ghh,*ghl,*gsch,*gscl,*gqfh,*gqfl,*gfbih,*gfbil;
    hf *gkqh,*gkql,*gvch,*gvcl,*gmth,*gmtl;
    hf *wqkvh,*wqkvl,*wfbh,*wfbl;
    cudaGetSymbolAddress((void**)&gh,   g_h);
    cudaGetSymbolAddress((void**)&gsc,  g_sc);
    cudaGetSymbolAddress((void**)&gqkv, g_qkv);
    cudaGetSymbolAddress((void**)&gfbo, g_fbout);
    cudaGetSymbolAddress((void**)&glg,  g_logits);
    cudaGetSymbolAddress((void**)&gwqk, g_wqk);
    cudaGetSymbolAddress((void**)&ghh,  g_hh);
    cudaGetSymbolAddress((void**)&ghl,  g_hl);
    cudaGetSymbolAddress((void**)&gsch, g_sch);
    cudaGetSymbolAddress((void**)&gscl, g_scl);
    cudaGetSymbolAddress((void**)&gqfh, g_qfh);
    cudaGetSymbolAddress((void**)&gqfl, g_qfl);
    cudaGetSymbolAddress((void**)&gfbih,g_fbih);
    cudaGetSymbolAddress((void**)&gfbil,g_fbil);
    cudaGetSymbolAddress((void**)&gkqh, g_kqh);
    cudaGetSymbolAddress((void**)&gkql, g_kql);
    cudaGetSymbolAddress((void**)&gvch, g_vch);
    cudaGetSymbolAddress((void**)&gvcl, g_vcl);
    cudaGetSymbolAddress((void**)&gmth, g_mth);
    cudaGetSymbolAddress((void**)&gmtl, g_mtl);
    cudaGetSymbolAddress((void**)&wqkvh,g_wqkvh);
    cudaGetSymbolAddress((void**)&wqkvl,g_wqkvl);
    cudaGetSymbolAddress((void**)&wfbh, g_wfbh);
    cudaGetSymbolAddress((void**)&wfbl, g_wfbl);

    const float A12 = 1.f/4096.f;
    const float AQM = 1.f/33554432.f;

    k_init<<<(NSEQ*32+255)/256,256>>>(se, lid);
    k_embed<<<dim3(NSEQ,BBn),256>>>(di, dou, ti, tok, seg);
    k_copy<<<(MROWS*DD/4)/256,256>>>();
    k_wqk<<<(3*DSLOT*256+255)/256,256>>>(Wkr, Wq);
    k_wsplit_all<<<(720896+255)/256,256>>>(Wqkv, Wfb);

    for (int pas=0; pas<2; pas++){
        if (pas > 0){
            k_fbprep<<<FBROWS,256>>>(pae);
            gemm_h(gfbih, gfbil, wfbh, wfbl, gfbo, 0, 0,
                   FBROWS, 256, 512, 512, 512, 256,
                   1,1, 0,0, 0,0, 0,0, 1, A12);
            k_fbapply<<<(FBROWS*256)/256,256>>>(bfb);
            k_copy<<<(MROWS*DD/4)/256,256>>>();
        }
        for (int l=0; l<LL; l++){
            for (int it=0; it<2; it++){
                k_cachekq<<<dim3(48,BBn),256>>>(gwqk + (size_t)l*DSLOT*256,
                                                Wvr + (size_t)l*DSLOT*256);
                gemm_h(ghh, ghl, gkqh, gkql, gsc, 0, 0,
                       NSEQ, 64, 256, 256, 256, 64,
                       BBn,1, (long)NSEQ*256,0, 64*256,0, (long)NSEQ*64,0, 1, A12);
                k_softrg<<<MROWS/8,256>>>(Wg, bg, l);
                gemm_h(gsch, gscl, gvch, gvcl, gh, ghh, ghl,
                       NSEQ, 256, 64, 64, 64, 256,
                       BBn,1, (long)NSEQ*64,0, 16384,0, (long)NSEQ*256,0, 7, 1.f/65536.f);
                gemm_h(ghh, ghl, wqkvh + (size_t)l*768*256, wqkvl + (size_t)l*768*256,
                       gqkv, 0, 0, MROWS, 768, 256, 256, 256, 768,
                       1,1, 0,0, 0,0, 0,0, 1, A12);
                k_kvacc<<<dim3(KVCH,64),256>>>();
                k_kvred<<<1024,256>>>();
                k_mtqf<<<MT_BLOCKS + QF_BLOCKS,256>>>(Wo + (size_t)l*256*256);
                gemm_h(gqfh, gqfl, gmth, gmtl, gh, ghh, ghl,
                       NSEQ, 256, 256, 256, 256, 256,
                       BBn,1, (long)NSEQ*256,0, 65536,0, (long)NSEQ*256,0, 7, AQM);
                k_wproj<<<262144/256,256>>>(Wwk + (size_t)l*256*128,
                                            Wwv + (size_t)l*256*128);
                k_write<<<BBn*16,128>>>(Wwg, bwg, l, it, pas);
            }
        }
        if (pas == 0) k_logits<<<FBROWS/16,256>>>(Wout, bout, glg);
        else          k_logits<<<FBROWS/16,256>>>(Wout, bout, (float*)d_out);
    }
}